// round 7
// baseline (speedup 1.0000x reference)
#include <cuda_runtime.h>
#include <cuda_bf16.h>
#include <cstdint>

// Problem constants (fixed by the dataset)
#define B_DIM   16
#define N_DIM   50000          // divisible by 8
#define E_DIM   1600000        // divisible by 4
#define CAP     112            // per-node bucket capacity (true max degree ~63)
#define PREP_T  (4 * N_DIM)    // 200000 prep threads
#define EDGE_T  (E_DIM / 4)    // 400000 bucketing threads (4 edges each)
#define CLAMP_MIN_F (-10.0f)
#define CLAMP_MAX_F ( 10.0f)
#define EPS_F   (1e-6f)

// Transposed (N, B) scratch: each node's 16 batch values contiguous (64B).
__device__ float    g_ET [N_DIM * B_DIM];   // E transposed
__device__ float    g_OT [N_DIM * B_DIM];   // o_pre transposed
__device__ float    g_ACC[N_DIM * B_DIM];   // E + chem (accumulator init)
__device__ unsigned g_cnt[N_DIM];           // per-dst bucket fill counters
__device__ int2     g_edge[(size_t)N_DIM * CAP];  // (src, w-bits) bucketed by dst

// ---------------------------------------------------------------------------
// Kernel 1 (after memset of g_cnt): fused prep + edge bucketing.
// Threads [0, PREP_T): q-split transpose (R3's latency-optimal layout).
// Threads [PREP_T, PREP_T+EDGE_T): each handles 4 consecutive edges with
//   vectorized int4/float4 index loads and 4 independent atomic->store
//   chains (4x MLP on the ~318cyc ATOMG latency).
// ---------------------------------------------------------------------------
__global__ void __launch_bounds__(256)
prep_scatter_kernel(const float* __restrict__ chem,
                    const float* __restrict__ E,
                    const float* __restrict__ o_pre,
                    const float* __restrict__ w,
                    const int*   __restrict__ src,
                    const int*   __restrict__ dst)
{
    int tid = blockIdx.x * blockDim.x + threadIdx.x;

    if (tid < PREP_T) {
        int q = tid / N_DIM;          // 0..3 (batch quad)
        int n = tid - q * N_DIM;      // node

        float et[4], ot[4], ac[4];
        #pragma unroll
        for (int j = 0; j < 4; j++) {
            int b = q * 4 + j;
            float e = __ldg(&E    [b * N_DIM + n]);
            float o = __ldg(&o_pre[b * N_DIM + n]);
            float c = __ldg(&chem [b * N_DIM + n]);
            et[j] = e;
            ot[j] = o;
            ac[j] = e + c;            // fold chem_influence into accumulator init
        }

        int t = n * B_DIM + q * 4;
        *reinterpret_cast<float4*>(&g_ET [t]) = make_float4(et[0], et[1], et[2], et[3]);
        *reinterpret_cast<float4*>(&g_OT [t]) = make_float4(ot[0], ot[1], ot[2], ot[3]);
        *reinterpret_cast<float4*>(&g_ACC[t]) = make_float4(ac[0], ac[1], ac[2], ac[3]);
    } else {
        int t = tid - PREP_T;
        if (t < EDGE_T) {
            int e0 = t * 4;
            const int4   s4 = __ldg(reinterpret_cast<const int4*>(&src[e0]));
            const int4   d4 = __ldg(reinterpret_cast<const int4*>(&dst[e0]));
            const float4 w4 = __ldg(reinterpret_cast<const float4*>(&w[e0]));

            int   ds[4] = {d4.x, d4.y, d4.z, d4.w};
            int   ss[4] = {s4.x, s4.y, s4.z, s4.w};
            float ws[4] = {w4.x, w4.y, w4.z, w4.w};

            unsigned pos[4];
            #pragma unroll
            for (int j = 0; j < 4; j++)         // 4 independent atomics in flight
                pos[j] = atomicAdd(&g_cnt[ds[j]], 1u);
            #pragma unroll
            for (int j = 0; j < 4; j++)
                if (pos[j] < CAP)
                    g_edge[(size_t)ds[j] * CAP + pos[j]] =
                        make_int2(ss[j], __float_as_int(ws[j]));
        }
    }
}

// ---------------------------------------------------------------------------
// Kernel 2: warp-per-node pull-gather + epilogue.
// Warp = one dst node d (deg is warp-uniform -> no divergence waste).
// lane = eo*4 + q: eo in 0..7 = edge slot, q in 0..3 = batch quad.
// Per iteration a warp consumes 8 bucket entries (contiguous 64B, quad-
// broadcast) and 8 Oj 64B blocks. En/ACC loaded once per node; accumulate
// in registers; shfl_xor-reduce over the eo bits; smem-stage outputs and
// write with full-sector coalescing.
// ---------------------------------------------------------------------------
__global__ void __launch_bounds__(256)
gather_final_kernel(const float* __restrict__ threshold,
                    const float* __restrict__ decay,
                    float* __restrict__ out)
{
    __shared__ float s_o[8][16];
    __shared__ float s_e[8][16];

    const int warp = threadIdx.x >> 5;          // 0..7
    const int lane = threadIdx.x & 31;
    const int eo   = lane >> 2;                 // 0..7
    const int q    = lane & 3;                  // 0..3
    const int d    = blockIdx.x * 8 + warp;     // node (grid sized exactly)

    unsigned deg = g_cnt[d];                    // uniform across warp
    if (deg > CAP) deg = CAP;
    const int2* el = &g_edge[(size_t)d * CAP];

    const int base = d * B_DIM + q * 4;
    const float4 En = *reinterpret_cast<const float4*>(&g_ET[base]);

    float4 acc;
    if (eo == 0) acc = *reinterpret_cast<const float4*>(&g_ACC[base]);
    else         acc = make_float4(0.f, 0.f, 0.f, 0.f);

    // Main loop: 2-way unrolled over edge slots (stride 8 per slot-group).
    unsigned i = eo;
    for (; i + 8 < deg; i += 16) {
        int2 e0 = __ldg(&el[i]);
        int2 e1 = __ldg(&el[i + 8]);
        float4 O0 = __ldg(reinterpret_cast<const float4*>(&g_OT[e0.x * B_DIM + q * 4]));
        float4 O1 = __ldg(reinterpret_cast<const float4*>(&g_OT[e1.x * B_DIM + q * 4]));
        float w0 = __int_as_float(e0.y);
        float w1 = __int_as_float(e1.y);
        acc.x += (O0.x >= En.x ? O0.x : -O0.x) * w0;
        acc.y += (O0.y >= En.y ? O0.y : -O0.y) * w0;
        acc.z += (O0.z >= En.z ? O0.z : -O0.z) * w0;
        acc.w += (O0.w >= En.w ? O0.w : -O0.w) * w0;
        acc.x += (O1.x >= En.x ? O1.x : -O1.x) * w1;
        acc.y += (O1.y >= En.y ? O1.y : -O1.y) * w1;
        acc.z += (O1.z >= En.z ? O1.z : -O1.z) * w1;
        acc.w += (O1.w >= En.w ? O1.w : -O1.w) * w1;
    }
    if (i < deg) {
        int2 e0 = __ldg(&el[i]);
        float4 O0 = __ldg(reinterpret_cast<const float4*>(&g_OT[e0.x * B_DIM + q * 4]));
        float w0 = __int_as_float(e0.y);
        acc.x += (O0.x >= En.x ? O0.x : -O0.x) * w0;
        acc.y += (O0.y >= En.y ? O0.y : -O0.y) * w0;
        acc.z += (O0.z >= En.z ? O0.z : -O0.z) * w0;
        acc.w += (O0.w >= En.w ? O0.w : -O0.w) * w0;
    }

    // Reduce over the eo bits (lane bits 2..4); q identity is preserved.
    #pragma unroll
    for (int off = 4; off <= 16; off <<= 1) {
        acc.x += __shfl_xor_sync(0xffffffffu, acc.x, off);
        acc.y += __shfl_xor_sync(0xffffffffu, acc.y, off);
        acc.z += __shfl_xor_sync(0xffffffffu, acc.z, off);
        acc.w += __shfl_xor_sync(0xffffffffu, acc.w, off);
    }

    // Epilogue on lanes eo==0 (one lane per batch quad), staged to smem.
    if (eo == 0) {
        float thr = __ldg(&threshold[d]);
        float dec = __ldg(&decay[d]);
        float Sa[4] = {acc.x, acc.y, acc.z, acc.w};
        float Ea[4] = {En.x, En.y, En.z, En.w};
        #pragma unroll
        for (int j = 0; j < 4; j++) {
            float S  = fminf(fmaxf(Sa[j], CLAMP_MIN_F), CLAMP_MAX_F);
            float Ev = Ea[j];
            bool  gt    = S > thr;
            float new_o = fmaxf(S - thr, 0.0f);
            bool  mask  = (!gt) && (fabsf(S - Ev) <= EPS_F);
            float new_e = gt ? new_o : (mask ? (Ev - dec) : S);
            s_o[warp][q * 4 + j] = new_o;
            s_e[warp][q * 4 + j] = new_e;
        }
    }
    __syncthreads();

    // Coalesced output write: 8 nodes x 16 batches x {new_o,new_e}.
    // tid -> (array a, batch b, local node di); consecutive tid = consecutive
    // di -> 32B contiguous runs (full sectors).
    {
        int tid = threadIdx.x;
        int a  = tid >> 7;          // 0: new_o, 1: new_e
        int r  = tid & 127;
        int b  = r >> 3;            // 0..15
        int di = r & 7;             // 0..7
        float v = a ? s_e[di][b] : s_o[di][b];
        out[a * (B_DIM * N_DIM) + b * N_DIM + blockIdx.x * 8 + di] = v;
    }
}

// ---------------------------------------------------------------------------
// Launch. Inputs (metadata order):
//   0 chem_influence (B,N) f32   1 E (B,N) f32       2 o_pre (B,N) f32
//   3 w (E,) f32                 4 threshold (N,) f32 5 decay (N,) f32
//   6 src (E,) i32               7 dst (E,) i32
// Output: new_o (B,N) then new_e (B,N) concatenated, f32.
// ---------------------------------------------------------------------------
extern "C" void kernel_launch(void* const* d_in, const int* in_sizes, int n_in,
                              void* d_out, int out_size)
{
    const float* chem  = (const float*)d_in[0];
    const float* E     = (const float*)d_in[1];
    const float* o_pre = (const float*)d_in[2];
    const float* w     = (const float*)d_in[3];
    const float* thr   = (const float*)d_in[4];
    const float* dec   = (const float*)d_in[5];
    const int*   src   = (const int*)  d_in[6];
    const int*   dst   = (const int*)  d_in[7];
    float* out = (float*)d_out;

    // Zero the bucket counters (graph-capturable, no allocation).
    void* cnt_ptr = nullptr;
    cudaGetSymbolAddress(&cnt_ptr, g_cnt);
    cudaMemsetAsync(cnt_ptr, 0, N_DIM * sizeof(unsigned));

    const int THREADS = 256;
    int fused_blocks  = (PREP_T + EDGE_T + THREADS - 1) / THREADS;  // 2344
    int gather_blocks = N_DIM / 8;                                  // 6250

    prep_scatter_kernel<<<fused_blocks,  THREADS>>>(chem, E, o_pre, w, src, dst);
    gather_final_kernel<<<gather_blocks, THREADS>>>(thr, dec, out);
}

// round 8
// speedup vs baseline: 1.2454x; 1.2454x over previous
#include <cuda_runtime.h>
#include <cuda_bf16.h>
#include <cstdint>

// Problem constants (fixed by the dataset)
#define B_DIM   16
#define N_DIM   50000
#define E_DIM   1600000        // even
#define CLAMP_MIN_F (-10.0f)
#define CLAMP_MAX_F ( 10.0f)
#define EPS_F   (1e-6f)

// Transposed (N, B) scratch: each node's 16 batch values are contiguous (64B).
// 3 x 3.2MB = 9.6MB -> fully L2-resident.
__device__ float g_ET [N_DIM * B_DIM];   // E transposed
__device__ float g_OT [N_DIM * B_DIM];   // o_pre transposed
__device__ float g_ACC[N_DIM * B_DIM];   // accumulator, init to E + chem

// ---------------------------------------------------------------------------
// Kernel A: transpose + init accumulator, q-split node-major (R3, known-good:
// at the LTS roofline). tid = q*N + n; coalesced input LDGs; full-sector
// 16B stores at 64B stride.
// ---------------------------------------------------------------------------
__global__ void __launch_bounds__(256)
prep_kernel(const float* __restrict__ chem,
            const float* __restrict__ E,
            const float* __restrict__ o_pre)
{
    int tid = blockIdx.x * blockDim.x + threadIdx.x;
    if (tid >= 4 * N_DIM) return;
    int q = tid / N_DIM;          // 0..3 (batch quad)
    int n = tid - q * N_DIM;      // node

    float et[4], ot[4], ac[4];
    #pragma unroll
    for (int j = 0; j < 4; j++) {
        int b = q * 4 + j;
        float e = __ldg(&E    [b * N_DIM + n]);
        float o = __ldg(&o_pre[b * N_DIM + n]);
        float c = __ldg(&chem [b * N_DIM + n]);
        et[j] = e;
        ot[j] = o;
        ac[j] = e + c;            // fold chem_influence into accumulator init
    }

    int t = n * B_DIM + q * 4;
    *reinterpret_cast<float4*>(&g_ET [t]) = make_float4(et[0], et[1], et[2], et[3]);
    *reinterpret_cast<float4*>(&g_OT [t]) = make_float4(ot[0], ot[1], ot[2], ot[3]);
    *reinterpret_cast<float4*>(&g_ACC[t]) = make_float4(ac[0], ac[1], ac[2], ac[3]);
}

// ---------------------------------------------------------------------------
// Kernel B: edge scatter, 2 edges per thread, 4 lanes per edge-pair-quad.
// t: e-pair = t>>2, q = t&3. Each thread runs two fully independent
// gather->compare->RED chains (2x MLP vs R3), with the quad's 4 lanes
// loading contiguous 16B pieces of each edge's 64B block (one 64B request
// per quad). red.global.add.v4.f32 -> no-return L2-side add.
// ---------------------------------------------------------------------------
__global__ void __launch_bounds__(256)
edge_kernel(const float* __restrict__ w,
            const int*   __restrict__ src,
            const int*   __restrict__ dst)
{
    int t = blockIdx.x * blockDim.x + threadIdx.x;
    if (t >= (E_DIM / 2) * 4) return;
    int ep = t >> 2;              // edge pair index
    int q  = t & 3;               // batch quad
    int e0 = ep * 2;
    int e1 = e0 + 1;

    int   s0 = __ldg(&src[e0]);
    int   d0 = __ldg(&dst[e0]);
    float w0 = __ldg(&w[e0]);
    int   s1 = __ldg(&src[e1]);
    int   d1 = __ldg(&dst[e1]);
    float w1 = __ldg(&w[e1]);

    const float4 O0 = __ldg(reinterpret_cast<const float4*>(&g_OT[s0 * B_DIM + q * 4]));
    const float4 E0 = __ldg(reinterpret_cast<const float4*>(&g_ET[d0 * B_DIM + q * 4]));
    const float4 O1 = __ldg(reinterpret_cast<const float4*>(&g_OT[s1 * B_DIM + q * 4]));
    const float4 E1 = __ldg(reinterpret_cast<const float4*>(&g_ET[d1 * B_DIM + q * 4]));

    float4 c0, c1;
    c0.x = (O0.x >= E0.x) ? (O0.x * w0) : (-O0.x * w0);
    c0.y = (O0.y >= E0.y) ? (O0.y * w0) : (-O0.y * w0);
    c0.z = (O0.z >= E0.z) ? (O0.z * w0) : (-O0.z * w0);
    c0.w = (O0.w >= E0.w) ? (O0.w * w0) : (-O0.w * w0);
    c1.x = (O1.x >= E1.x) ? (O1.x * w1) : (-O1.x * w1);
    c1.y = (O1.y >= E1.y) ? (O1.y * w1) : (-O1.y * w1);
    c1.z = (O1.z >= E1.z) ? (O1.z * w1) : (-O1.z * w1);
    c1.w = (O1.w >= E1.w) ? (O1.w * w1) : (-O1.w * w1);

    float* p0 = &g_ACC[d0 * B_DIM + q * 4];
    asm volatile("red.global.add.v4.f32 [%0], {%1, %2, %3, %4};"
                 :: "l"(p0), "f"(c0.x), "f"(c0.y), "f"(c0.z), "f"(c0.w)
                 : "memory");
    float* p1 = &g_ACC[d1 * B_DIM + q * 4];
    asm volatile("red.global.add.v4.f32 [%0], {%1, %2, %3, %4};"
                 :: "l"(p1), "f"(c1.x), "f"(c1.y), "f"(c1.z), "f"(c1.w)
                 : "memory");
}

// ---------------------------------------------------------------------------
// Kernel C: epilogue, q-split node-major (tid = q*N + n).
// ACC and E both read as one contiguous LDG.128 each (E from g_ET, saving 3
// strided loads); threshold/decay and the 8 output stores are coalesced.
// ---------------------------------------------------------------------------
__global__ void __launch_bounds__(256)
final_kernel(const float* __restrict__ threshold,
             const float* __restrict__ decay,
             float* __restrict__ out)
{
    int tid = blockIdx.x * blockDim.x + threadIdx.x;
    if (tid >= 4 * N_DIM) return;
    int q = tid / N_DIM;
    int n = tid - q * N_DIM;

    int base = n * B_DIM + q * 4;
    float4 Sv = *reinterpret_cast<const float4*>(&g_ACC[base]);
    float4 Ev = *reinterpret_cast<const float4*>(&g_ET [base]);
    float  thr = __ldg(&threshold[n]);
    float  dec = __ldg(&decay[n]);

    float Sa[4] = {Sv.x, Sv.y, Sv.z, Sv.w};
    float Ea[4] = {Ev.x, Ev.y, Ev.z, Ev.w};
    #pragma unroll
    for (int j = 0; j < 4; j++) {
        int b = q * 4 + j;
        float S  = fminf(fmaxf(Sa[j], CLAMP_MIN_F), CLAMP_MAX_F);
        float ev = Ea[j];
        bool  gt    = S > thr;
        float new_o = fmaxf(S - thr, 0.0f);
        bool  mask  = (!gt) && (fabsf(S - ev) <= EPS_F);
        float new_e = gt ? new_o : (mask ? (ev - dec) : S);

        out[b * N_DIM + n]                 = new_o;
        out[B_DIM * N_DIM + b * N_DIM + n] = new_e;
    }
}

// ---------------------------------------------------------------------------
// Launch. Inputs (metadata order):
//   0 chem_influence (B,N) f32   1 E (B,N) f32       2 o_pre (B,N) f32
//   3 w (E,) f32                 4 threshold (N,) f32 5 decay (N,) f32
//   6 src (E,) i32               7 dst (E,) i32
// Output: new_o (B,N) then new_e (B,N) concatenated, f32.
// ---------------------------------------------------------------------------
extern "C" void kernel_launch(void* const* d_in, const int* in_sizes, int n_in,
                              void* d_out, int out_size)
{
    const float* chem  = (const float*)d_in[0];
    const float* E     = (const float*)d_in[1];
    const float* o_pre = (const float*)d_in[2];
    const float* w     = (const float*)d_in[3];
    const float* thr   = (const float*)d_in[4];
    const float* dec   = (const float*)d_in[5];
    const int*   src   = (const int*)  d_in[6];
    const int*   dst   = (const int*)  d_in[7];
    float* out = (float*)d_out;

    const int THREADS = 256;
    int qn_blocks   = (4 * N_DIM + THREADS - 1) / THREADS;          // 782
    int edge_blocks = ((E_DIM / 2) * 4 + THREADS - 1) / THREADS;    // 12500

    prep_kernel <<<qn_blocks,   THREADS>>>(chem, E, o_pre);
    edge_kernel <<<edge_blocks, THREADS>>>(w, src, dst);
    final_kernel<<<qn_blocks,   THREADS>>>(thr, dec, out);
}

// round 9
// speedup vs baseline: 1.2688x; 1.0188x over previous
#include <cuda_runtime.h>
#include <cuda_bf16.h>
#include <cstdint>

// Problem constants (fixed by the dataset)
#define B_DIM   16
#define N_DIM   50000
#define E_DIM   1600000
#define BN      (B_DIM * N_DIM)
#define CLAMP_MIN_F (-10.0f)
#define CLAMP_MAX_F ( 10.0f)
#define EPS_F   (1e-6f)

// Transposed (N, B) scratch: each node's 16 batch values are contiguous (64B).
// 3 x 3.2MB = 9.6MB -> fully L2-resident.
__device__ float g_ET [N_DIM * B_DIM];   // E transposed
__device__ float g_OT [N_DIM * B_DIM];   // o_pre transposed
__device__ float g_ACC[N_DIM * B_DIM];   // accumulator, init to E + chem

// ---------------------------------------------------------------------------
// Kernel A: transpose + init accumulator, smem-staged so BOTH sides are dense.
// Block = 64 nodes. Phase 1 (q-split): warp = 32 consecutive n, fixed batch
// group -> every LDG is a dense 128B line. Stage to smem. Phase 2 (node-quad):
// 4 adjacent lanes emit one node's contiguous 64B float4s -> warp stores 512B
// contiguous per array (full sectors; ~4x fewer store wavefronts than the
// strided q-split stores).
// ---------------------------------------------------------------------------
__global__ void __launch_bounds__(256)
prep_kernel(const float* __restrict__ chem,
            const float* __restrict__ E,
            const float* __restrict__ o_pre)
{
    __shared__ float s_e[B_DIM][65];
    __shared__ float s_o[B_DIM][65];
    __shared__ float s_a[B_DIM][65];

    const int n0 = blockIdx.x * 64;
    const int t  = threadIdx.x;

    // Phase 1: dense loads (q-split within the block).
    {
        int q  = t >> 6;          // 0..3
        int nl = t & 63;          // 0..63
        int n  = n0 + nl;
        if (n < N_DIM) {
            #pragma unroll
            for (int j = 0; j < 4; j++) {
                int b = q * 4 + j;
                float e = __ldg(&E    [b * N_DIM + n]);
                float o = __ldg(&o_pre[b * N_DIM + n]);
                float c = __ldg(&chem [b * N_DIM + n]);
                s_e[b][nl] = e;
                s_o[b][nl] = o;
                s_a[b][nl] = e + c;   // fold chem_influence into accumulator init
            }
        }
    }
    __syncthreads();

    // Phase 2: dense stores (node-quad within the block).
    {
        int ni = t >> 2;          // 0..63 (local node)
        int qq = t & 3;           // 0..3  (batch quad)
        int n  = n0 + ni;
        if (n < N_DIM) {
            int b0 = qq * 4;
            float4 ve = make_float4(s_e[b0][ni], s_e[b0+1][ni], s_e[b0+2][ni], s_e[b0+3][ni]);
            float4 vo = make_float4(s_o[b0][ni], s_o[b0+1][ni], s_o[b0+2][ni], s_o[b0+3][ni]);
            float4 va = make_float4(s_a[b0][ni], s_a[b0+1][ni], s_a[b0+2][ni], s_a[b0+3][ni]);
            int base = n * B_DIM + b0;
            *reinterpret_cast<float4*>(&g_ET [base]) = ve;
            *reinterpret_cast<float4*>(&g_OT [base]) = vo;
            *reinterpret_cast<float4*>(&g_ACC[base]) = va;
        }
    }
}

// ---------------------------------------------------------------------------
// Kernel B: edge scatter (R3's known-good form — at the LTS roofline).
// 4 lanes per edge; each lane owns one batch quad (float4). Quad lanes load
// contiguous 16B pieces of the edge's 64B block (one 64B request per quad).
// red.global.add.v4.f32 -> no-return L2-side add, one RED.128 per lane.
// ---------------------------------------------------------------------------
__global__ void __launch_bounds__(256)
edge_kernel(const float* __restrict__ w,
            const int*   __restrict__ src,
            const int*   __restrict__ dst)
{
    int t = blockIdx.x * blockDim.x + threadIdx.x;
    if (t >= E_DIM * 4) return;
    int e = t >> 2;
    int q = t & 3;

    int   s  = __ldg(&src[e]);
    int   d  = __ldg(&dst[e]);
    float wv = __ldg(&w[e]);

    const float4 Oj = __ldg(reinterpret_cast<const float4*>(&g_OT[s * B_DIM + q * 4]));
    const float4 En = __ldg(reinterpret_cast<const float4*>(&g_ET[d * B_DIM + q * 4]));

    float4 c;
    c.x = (Oj.x >= En.x) ? (Oj.x * wv) : (-Oj.x * wv);
    c.y = (Oj.y >= En.y) ? (Oj.y * wv) : (-Oj.y * wv);
    c.z = (Oj.z >= En.z) ? (Oj.z * wv) : (-Oj.z * wv);
    c.w = (Oj.w >= En.w) ? (Oj.w * wv) : (-Oj.w * wv);

    float* p = &g_ACC[d * B_DIM + q * 4];
    asm volatile("red.global.add.v4.f32 [%0], {%1, %2, %3, %4};"
                 :: "l"(p), "f"(c.x), "f"(c.y), "f"(c.z), "f"(c.w)
                 : "memory");
}

// ---------------------------------------------------------------------------
// Kernel C: epilogue, smem-staged (mirror of prep). Phase 1 (node-quad):
// dense 64B/node loads of ACC and ET, epilogue math, stage results. Phase 2
// (q-split): dense 128B warp stores of both output planes.
// ---------------------------------------------------------------------------
__global__ void __launch_bounds__(256)
final_kernel(const float* __restrict__ threshold,
             const float* __restrict__ decay,
             float* __restrict__ out)
{
    __shared__ float s_no[B_DIM][65];
    __shared__ float s_ne[B_DIM][65];

    const int n0 = blockIdx.x * 64;
    const int t  = threadIdx.x;

    // Phase 1: dense loads + epilogue math.
    {
        int ni = t >> 2;
        int qq = t & 3;
        int n  = n0 + ni;
        if (n < N_DIM) {
            int base = n * B_DIM + qq * 4;
            float4 Sv = *reinterpret_cast<const float4*>(&g_ACC[base]);
            float4 Ev = *reinterpret_cast<const float4*>(&g_ET [base]);
            float thr = __ldg(&threshold[n]);   // broadcast across the quad
            float dec = __ldg(&decay[n]);

            float Sa[4] = {Sv.x, Sv.y, Sv.z, Sv.w};
            float Ea[4] = {Ev.x, Ev.y, Ev.z, Ev.w};
            #pragma unroll
            for (int j = 0; j < 4; j++) {
                int b = qq * 4 + j;
                float S  = fminf(fmaxf(Sa[j], CLAMP_MIN_F), CLAMP_MAX_F);
                float ev = Ea[j];
                bool  gt    = S > thr;
                float new_o = fmaxf(S - thr, 0.0f);
                bool  mask  = (!gt) && (fabsf(S - ev) <= EPS_F);
                float new_e = gt ? new_o : (mask ? (ev - dec) : S);
                s_no[b][ni] = new_o;
                s_ne[b][ni] = new_e;
            }
        }
    }
    __syncthreads();

    // Phase 2: dense stores (q-split).
    {
        int q  = t >> 6;
        int nl = t & 63;
        int n  = n0 + nl;
        if (n < N_DIM) {
            #pragma unroll
            for (int j = 0; j < 4; j++) {
                int b = q * 4 + j;
                out[b * N_DIM + n]      = s_no[b][nl];
                out[BN + b * N_DIM + n] = s_ne[b][nl];
            }
        }
    }
}

// ---------------------------------------------------------------------------
// Launch. Inputs (metadata order):
//   0 chem_influence (B,N) f32   1 E (B,N) f32       2 o_pre (B,N) f32
//   3 w (E,) f32                 4 threshold (N,) f32 5 decay (N,) f32
//   6 src (E,) i32               7 dst (E,) i32
// Output: new_o (B,N) then new_e (B,N) concatenated, f32.
// ---------------------------------------------------------------------------
extern "C" void kernel_launch(void* const* d_in, const int* in_sizes, int n_in,
                              void* d_out, int out_size)
{
    const float* chem  = (const float*)d_in[0];
    const float* E     = (const float*)d_in[1];
    const float* o_pre = (const float*)d_in[2];
    const float* w     = (const float*)d_in[3];
    const float* thr   = (const float*)d_in[4];
    const float* dec   = (const float*)d_in[5];
    const int*   src   = (const int*)  d_in[6];
    const int*   dst   = (const int*)  d_in[7];
    float* out = (float*)d_out;

    const int THREADS = 256;
    int node_blocks = (N_DIM + 63) / 64;                        // 782
    int edge_blocks = (E_DIM * 4 + THREADS - 1) / THREADS;      // 25000

    prep_kernel <<<node_blocks, THREADS>>>(chem, E, o_pre);
    edge_kernel <<<edge_blocks, THREADS>>>(w, src, dst);
    final_kernel<<<node_blocks, THREADS>>>(thr, dec, out);
}